// round 16
// baseline (speedup 1.0000x reference)
#include <cuda_runtime.h>
#include <cuda_fp16.h>

// Problem constants (fixed by the dataset)
#define NN 100000
#define EE 1600000

// Scratch: __device__ globals only, referenced ONLY from device code
// (host-side symbol use binds the ATS-dereferenceable host shadow -> R2 bug).
__device__ int    g_is64;
__device__ int    g_deg[NN];
__device__ int    g_off[NN];
__device__ int    g_cur[NN];
__device__ int    g_csr[EE];
__device__ int    g_bsum[1024];
__device__ __half g_t1[NN * 32];   // fp16 intermediates (gathered)
__device__ float  g_a1[NN * 32];   // fp32 accumulators
__device__ __half g_t2[NN * 48];
__device__ float  g_a2[NN * 48];
__device__ __half g_t3[NN * 16];

// Packed fp32x2 helpers (Blackwell FFMA2 — exact fp32, 2 FMAs/inst)
__device__ __forceinline__ unsigned long long fma2(
    unsigned long long a, unsigned long long b, unsigned long long c) {
    unsigned long long d;
    asm("fma.rn.f32x2 %0, %1, %2, %3;" : "=l"(d) : "l"(a), "l"(b), "l"(c));
    return d;
}
__device__ __forceinline__ unsigned long long add2(
    unsigned long long a, unsigned long long b) {
    unsigned long long d;
    asm("add.rn.f32x2 %0, %1, %2;" : "=l"(d) : "l"(a), "l"(b));
    return d;
}
__device__ __forceinline__ unsigned long long bcast2(float v) {
    unsigned long long d;
    asm("mov.b64 %0, {%1, %1};" : "=l"(d) : "f"(v));
    return d;
}
// pack fp32x2 (u64) -> f16x2 (u32), memory order preserved (lo first)
__device__ __forceinline__ unsigned int f32x2_to_h2(unsigned long long v) {
    float lo, hi; unsigned int r;
    asm("mov.b64 {%0, %1}, %2;" : "=f"(lo), "=f"(hi) : "l"(v));
    asm("cvt.rn.f16x2.f32 %0, %1, %2;" : "=r"(r) : "f"(hi), "f"(lo));
    return r;
}

// ---------------------------------------------------------------------------
// CSR build (side stream, hidden behind node1)
// ---------------------------------------------------------------------------
__global__ __launch_bounds__(256) void k_init(const void* __restrict__ ei, int N) {
    int i = blockIdx.x * blockDim.x + threadIdx.x;
    if (i < N) g_deg[i] = 0;
    if (i == 0) {
        const long long* p = (const long long*)ei;
        int ok = 1;
        for (int q = 0; q < 64; q++) {
            long long v = p[q];
            if (v < 0 || v >= (long long)N) { ok = 0; break; }
        }
        g_is64 = ok;
    }
}

__global__ __launch_bounds__(256) void k_hist(const void* __restrict__ ei, int E) {
    int i = blockIdx.x * blockDim.x + threadIdx.x;
    if (i >= E) return;
    int d;
    if (g_is64) d = (int)((const long long*)ei)[E + i];
    else        d = ((const int*)ei)[E + i];
    atomicAdd(&g_deg[d], 1);
}

__global__ __launch_bounds__(256) void k_scanA(int N) {
    __shared__ int s[256];
    int b = blockIdx.x, t = threadIdx.x;
    int base = b * 1024 + t * 4;
    int sum = 0;
#pragma unroll
    for (int i = 0; i < 4; i++) {
        int idx = base + i;
        if (idx < N) sum += g_deg[idx];
    }
    s[t] = sum;
    __syncthreads();
#pragma unroll
    for (int d = 128; d > 0; d >>= 1) {
        if (t < d) s[t] += s[t + d];
        __syncthreads();
    }
    if (t == 0) g_bsum[b] = s[0];
}

__global__ __launch_bounds__(256) void k_scanC(int N, int NB) {
    __shared__ int sb_[128];
    __shared__ int s[256];
    int b = blockIdx.x, t = threadIdx.x;
    if (t < 128) sb_[t] = (t < NB) ? g_bsum[t] : 0;
    __syncthreads();
#pragma unroll
    for (int d = 1; d < 128; d <<= 1) {
        int x = (t >= d && t < 128) ? sb_[t - d] : 0;
        __syncthreads();
        if (t < 128) sb_[t] += x;
        __syncthreads();
    }
    int boff = (b == 0) ? 0 : sb_[b - 1];

    int base = b * 1024 + t * 4;
    int v[4];
    int sum = 0;
#pragma unroll
    for (int i = 0; i < 4; i++) {
        int idx = base + i;
        v[i] = (idx < N) ? g_deg[idx] : 0;
        sum += v[i];
    }
    s[t] = sum;
    __syncthreads();
    for (int d = 1; d < 256; d <<= 1) {
        int x = (t >= d) ? s[t - d] : 0;
        __syncthreads();
        s[t] += x;
        __syncthreads();
    }
    int run = s[t] - sum + boff;
#pragma unroll
    for (int i = 0; i < 4; i++) {
        int idx = base + i;
        if (idx < N) {
            g_off[idx] = run;
            g_cur[idx] = run;
            run += v[i];
        }
    }
}

__global__ __launch_bounds__(256) void k_scatter(const void* __restrict__ ei, int E) {
    int i = blockIdx.x * blockDim.x + threadIdx.x;
    if (i >= E) return;
    int s, d;
    if (g_is64) {
        const long long* p = (const long long*)ei;
        s = (int)p[i];
        d = (int)p[E + i];
    } else {
        const int* p = (const int*)ei;
        s = p[i];
        d = p[E + i];
    }
    int pos = atomicAdd(&g_cur[d], 1);
    g_csr[pos] = s;
}

// ---------------------------------------------------------------------------
// Dual-GEMM j-tile body, FFMA2 (weights/bias from smem)
// ---------------------------------------------------------------------------
#define JTILE_BODY2(IN, OUT)                                                   \
    unsigned long long at2[4], ar2[4];                                         \
    {                                                                          \
        ulonglong2 binit0 = *(const ulonglong2*)&sb[jt];                       \
        ulonglong2 binit1 = *(const ulonglong2*)&sb[jt + 4];                   \
        at2[0] = 0ull; at2[1] = 0ull; at2[2] = 0ull; at2[3] = 0ull;            \
        ar2[0] = binit0.x; ar2[1] = binit0.y;                                  \
        ar2[2] = binit1.x; ar2[3] = binit1.y;                                  \
    }                                                                          \
    _Pragma("unroll")                                                          \
    for (int k = 0; k < IN; k++) {                                             \
        unsigned long long hk2 = bcast2(h[k]);                                 \
        ulonglong2 wr01 = *(const ulonglong2*)&sWr[k * OUT + jt];              \
        ulonglong2 wr23 = *(const ulonglong2*)&sWr[k * OUT + jt + 4];          \
        ulonglong2 wo01 = *(const ulonglong2*)&sWo[k * OUT + jt];              \
        ulonglong2 wo23 = *(const ulonglong2*)&sWo[k * OUT + jt + 4];          \
        at2[0] = fma2(hk2, wr01.x, at2[0]);                                    \
        at2[1] = fma2(hk2, wr01.y, at2[1]);                                    \
        at2[2] = fma2(hk2, wr23.x, at2[2]);                                    \
        at2[3] = fma2(hk2, wr23.y, at2[3]);                                    \
        ar2[0] = fma2(hk2, wo01.x, ar2[0]);                                    \
        ar2[1] = fma2(hk2, wo01.y, ar2[1]);                                    \
        ar2[2] = fma2(hk2, wo23.x, ar2[2]);                                    \
        ar2[3] = fma2(hk2, wo23.y, ar2[3]);                                    \
    }

// pack the 8 rel-outputs of a j-tile into 8 halves (one uint4)
#define T_TILE_H4()                                                            \
    make_uint4(f32x2_to_h2(at2[0]), f32x2_to_h2(at2[1]),                       \
               f32x2_to_h2(at2[2]), f32x2_to_h2(at2[3]))

// ---------------------------------------------------------------------------
// K1: layer 1 node kernel. h0 = concat(x[48], ax[16]) -> 64
//     t1(half) = h0 @ W1_rel ; a1(f32) = h0 @ W1_root + b1
// ---------------------------------------------------------------------------
__global__ __launch_bounds__(256) void k_node1(
    const float* __restrict__ x, const float* __restrict__ ax,
    const float* __restrict__ Wrel, const float* __restrict__ Wroot,
    const float* __restrict__ b, int N)
{
    __shared__ __align__(16) float sWr[64 * 32];
    __shared__ __align__(16) float sWo[64 * 32];
    __shared__ __align__(16) float sb[32];
    for (int t = threadIdx.x; t < 64 * 32; t += 256) { sWr[t] = Wrel[t]; sWo[t] = Wroot[t]; }
    if (threadIdx.x < 32) sb[threadIdx.x] = b[threadIdx.x];
    __syncthreads();

    int i = blockIdx.x * 256 + threadIdx.x;
    if (i >= N) return;

    float h[64];
    const float4* xp = (const float4*)(x + (size_t)i * 48);
#pragma unroll
    for (int q = 0; q < 12; q++) {
        float4 v = xp[q];
        h[4*q] = v.x; h[4*q+1] = v.y; h[4*q+2] = v.z; h[4*q+3] = v.w;
    }
    const float4* ap = (const float4*)(ax + (size_t)i * 16);
#pragma unroll
    for (int q = 0; q < 4; q++) {
        float4 v = ap[q];
        h[48+4*q] = v.x; h[48+4*q+1] = v.y; h[48+4*q+2] = v.z; h[48+4*q+3] = v.w;
    }

    __half* t1 = g_t1 + (size_t)i * 32;
    float*  a1 = g_a1 + (size_t)i * 32;
#pragma unroll 1
    for (int jt = 0; jt < 32; jt += 8) {
        JTILE_BODY2(64, 32)
        *(uint4*)&t1[jt] = T_TILE_H4();
        *(ulonglong2*)&a1[jt]     = make_ulonglong2(ar2[0], ar2[1]);
        *(ulonglong2*)&a1[jt + 4] = make_ulonglong2(ar2[2], ar2[3]);
    }
}

// ---------------------------------------------------------------------------
// K3: layer 2 node kernel. h1 = concat(relu(a1)[32], lf[16]) -> 48
// ---------------------------------------------------------------------------
__global__ __launch_bounds__(256) void k_node2(
    const float* __restrict__ lf,
    const float* __restrict__ Wrel, const float* __restrict__ Wroot,
    const float* __restrict__ b, int N)
{
    __shared__ __align__(16) float sWr[48 * 48];
    __shared__ __align__(16) float sWo[48 * 48];
    __shared__ __align__(16) float sb[48];
    for (int t = threadIdx.x; t < 48 * 48; t += 256) { sWr[t] = Wrel[t]; sWo[t] = Wroot[t]; }
    if (threadIdx.x < 48) sb[threadIdx.x] = b[threadIdx.x];
    __syncthreads();

    int i = blockIdx.x * 256 + threadIdx.x;
    if (i >= N) return;

    float h[48];
    const float4* a1p = (const float4*)(g_a1 + (size_t)i * 32);
#pragma unroll
    for (int q = 0; q < 8; q++) {
        float4 v = a1p[q];
        h[4*q]   = fmaxf(v.x, 0.0f);
        h[4*q+1] = fmaxf(v.y, 0.0f);
        h[4*q+2] = fmaxf(v.z, 0.0f);
        h[4*q+3] = fmaxf(v.w, 0.0f);
    }
    const float4* lp = (const float4*)(lf + (size_t)i * 16);
#pragma unroll
    for (int q = 0; q < 4; q++) {
        float4 v = lp[q];
        h[32+4*q] = v.x; h[32+4*q+1] = v.y; h[32+4*q+2] = v.z; h[32+4*q+3] = v.w;
    }

    __half* t2 = g_t2 + (size_t)i * 48;
    float*  a2 = g_a2 + (size_t)i * 48;
#pragma unroll 1
    for (int jt = 0; jt < 48; jt += 8) {
        JTILE_BODY2(48, 48)
        *(uint4*)&t2[jt] = T_TILE_H4();
        *(ulonglong2*)&a2[jt]     = make_ulonglong2(ar2[0], ar2[1]);
        *(ulonglong2*)&a2[jt + 4] = make_ulonglong2(ar2[2], ar2[3]);
    }
}

// ---------------------------------------------------------------------------
// K5: layer 3 node kernel. h2 = relu(a2)[48]
//     t3(half) = h2 @ W3_rel ; out = h2 @ W3_root + b3 + ax
// ---------------------------------------------------------------------------
__global__ __launch_bounds__(256) void k_node3(
    const float* __restrict__ ax,
    const float* __restrict__ Wrel, const float* __restrict__ Wroot,
    const float* __restrict__ b, float* __restrict__ out, int N)
{
    __shared__ __align__(16) float sWr[48 * 16];
    __shared__ __align__(16) float sWo[48 * 16];
    __shared__ __align__(16) float sb[16];
    for (int t = threadIdx.x; t < 48 * 16; t += 256) { sWr[t] = Wrel[t]; sWo[t] = Wroot[t]; }
    if (threadIdx.x < 16) sb[threadIdx.x] = b[threadIdx.x];
    __syncthreads();

    int i = blockIdx.x * 256 + threadIdx.x;
    if (i >= N) return;

    float h[48];
    const float4* a2p = (const float4*)(g_a2 + (size_t)i * 48);
#pragma unroll
    for (int q = 0; q < 12; q++) {
        float4 v = a2p[q];
        h[4*q]   = fmaxf(v.x, 0.0f);
        h[4*q+1] = fmaxf(v.y, 0.0f);
        h[4*q+2] = fmaxf(v.z, 0.0f);
        h[4*q+3] = fmaxf(v.w, 0.0f);
    }

    const ulonglong2* axp = (const ulonglong2*)(ax + (size_t)i * 16);
    __half* t3 = g_t3 + (size_t)i * 16;
    float*  o  = out + (size_t)i * 16;
#pragma unroll 1
    for (int jt = 0; jt < 16; jt += 8) {
        JTILE_BODY2(48, 16)
        ulonglong2 av0 = axp[jt / 4];
        ulonglong2 av1 = axp[jt / 4 + 1];
        *(uint4*)&t3[jt] = T_TILE_H4();
        *(ulonglong2*)&o[jt]      = make_ulonglong2(add2(ar2[0], av0.x),
                                                    add2(ar2[1], av0.y));
        *(ulonglong2*)&o[jt + 4]  = make_ulonglong2(add2(ar2[2], av1.x),
                                                    add2(ar2[3], av1.y));
    }
}

// ---------------------------------------------------------------------------
// CSR aggregation on fp16 rows: thread (node, 8-col chunk). CHH adjacent
// lanes cover one node's row -> coalesced. Accumulation in fp32.
// Row width = CHH*8 halves; acc row = CHH*8 floats.
// ---------------------------------------------------------------------------
template <int CHH>
__device__ __forceinline__ void agg_body_h(
    const __half* __restrict__ t, float* __restrict__ acc, int N)
{
    int tid = blockIdx.x * blockDim.x + threadIdx.x;
    if (tid >= N * CHH) return;
    int n = tid / CHH;
    int c = tid - n * CHH;
    const int ROW = CHH * 8;

    int beg = g_off[n];
    int end = beg + g_deg[n];

    float s0[8], s1[8];
#pragma unroll
    for (int q = 0; q < 8; q++) { s0[q] = 0.f; s1[q] = 0.f; }

    int j = beg;
    for (; j + 3 < end; j += 4) {
        int n0 = g_csr[j], n1 = g_csr[j+1], n2 = g_csr[j+2], n3 = g_csr[j+3];
        uint4 v0 = *(const uint4*)(t + (size_t)n0 * ROW + c * 8);
        uint4 v1 = *(const uint4*)(t + (size_t)n1 * ROW + c * 8);
        uint4 v2 = *(const uint4*)(t + (size_t)n2 * ROW + c * 8);
        uint4 v3 = *(const uint4*)(t + (size_t)n3 * ROW + c * 8);
        const __half2* h0 = (const __half2*)&v0;
        const __half2* h1 = (const __half2*)&v1;
        const __half2* h2 = (const __half2*)&v2;
        const __half2* h3 = (const __half2*)&v3;
#pragma unroll
        for (int q = 0; q < 4; q++) {
            float2 f0 = __half22float2(h0[q]);
            float2 f1 = __half22float2(h1[q]);
            float2 f2 = __half22float2(h2[q]);
            float2 f3 = __half22float2(h3[q]);
            s0[2*q]   += f0.x + f2.x;
            s0[2*q+1] += f0.y + f2.y;
            s1[2*q]   += f1.x + f3.x;
            s1[2*q+1] += f1.y + f3.y;
        }
    }
    for (; j < end; j++) {
        int ns = g_csr[j];
        uint4 v = *(const uint4*)(t + (size_t)ns * ROW + c * 8);
        const __half2* hp = (const __half2*)&v;
#pragma unroll
        for (int q = 0; q < 4; q++) {
            float2 f = __half22float2(hp[q]);
            s0[2*q]   += f.x;
            s0[2*q+1] += f.y;
        }
    }

    float* ap = acc + (size_t)n * ROW + c * 8;
    float4 cur0 = *(float4*)ap;
    float4 cur1 = *((float4*)ap + 1);
    *(float4*)ap = make_float4(cur0.x + s0[0] + s1[0], cur0.y + s0[1] + s1[1],
                               cur0.z + s0[2] + s1[2], cur0.w + s0[3] + s1[3]);
    *((float4*)ap + 1) = make_float4(cur1.x + s0[4] + s1[4], cur1.y + s0[5] + s1[5],
                                     cur1.z + s0[6] + s1[6], cur1.w + s0[7] + s1[7]);
}

__global__ __launch_bounds__(256) void k_agg1(int N) { agg_body_h<4>(g_t1, g_a1, N); }
__global__ __launch_bounds__(256) void k_agg2(int N) { agg_body_h<6>(g_t2, g_a2, N); }
__global__ __launch_bounds__(256) void k_agg3(float* __restrict__ out, int N) {
    agg_body_h<2>(g_t3, out, N);
}

// ---------------------------------------------------------------------------
// kernel_launch: CSR ‖ node1 -> agg1 -> node2 -> agg2 -> node3 -> agg3
// ---------------------------------------------------------------------------
extern "C" void kernel_launch(void* const* d_in, const int* in_sizes, int n_in,
                              void* d_out, int out_size)
{
    const float* x   = (const float*)d_in[0];
    const void*  ei  = d_in[1];
    const float* ax  = (const float*)d_in[2];
    const float* lf  = (const float*)d_in[3];
    const float* W1r = (const float*)d_in[4];
    const float* b1  = (const float*)d_in[5];
    const float* W1o = (const float*)d_in[6];
    const float* W2r = (const float*)d_in[7];
    const float* b2  = (const float*)d_in[8];
    const float* W2o = (const float*)d_in[9];
    const float* W3r = (const float*)d_in[10];
    const float* b3  = (const float*)d_in[11];
    const float* W3o = (const float*)d_in[12];
    float* out = (float*)d_out;

    const int N = in_sizes[0] / 48;
    const int E = in_sizes[1] / 2;

    const int TB = 256;
    const int nodeBlocks = (N + TB - 1) / TB;
    const int edgeBlocks = (E + TB - 1) / TB;
    const int NB = (N + 1023) / 1024;

    static cudaStream_t s2 = nullptr;
    static cudaEvent_t evFork = nullptr, evJoin = nullptr;
    if (!s2) {
        cudaStreamCreateWithFlags(&s2, cudaStreamNonBlocking);
        cudaEventCreateWithFlags(&evFork, cudaEventDisableTiming);
        cudaEventCreateWithFlags(&evJoin, cudaEventDisableTiming);
    }

    // Fork: CSR build on s2, node1 on the main (capture) stream.
    cudaEventRecord(evFork, 0);
    cudaStreamWaitEvent(s2, evFork, 0);

    k_init   <<<nodeBlocks, TB, 0, s2>>>(ei, N);
    k_hist   <<<edgeBlocks, TB, 0, s2>>>(ei, E);
    k_scanA  <<<NB, TB, 0, s2>>>(N);
    k_scanC  <<<NB, TB, 0, s2>>>(N, NB);
    k_scatter<<<edgeBlocks, TB, 0, s2>>>(ei, E);
    cudaEventRecord(evJoin, s2);

    // Layer 1 transform runs concurrently with the CSR build.
    k_node1<<<nodeBlocks, TB>>>(x, ax, W1r, W1o, b1, N);

    // Join: aggregation needs both CSR and t1.
    cudaStreamWaitEvent(0, evJoin, 0);
    k_agg1<<<((long long)N * 4 + TB - 1) / TB, TB>>>(N);

    // Layer 2
    k_node2<<<nodeBlocks, TB>>>(lf, W2r, W2o, b2, N);
    k_agg2<<<((long long)N * 6 + TB - 1) / TB, TB>>>(N);

    // Layer 3, accumulate straight into d_out
    k_node3<<<nodeBlocks, TB>>>(ax, W3r, W3o, b3, out, N);
    k_agg3<<<((long long)N * 2 + TB - 1) / TB, TB>>>(out, N);
}